// round 3
// baseline (speedup 1.0000x reference)
#include <cuda_runtime.h>

// Decoder: 8 batches of 32-segment piecewise-linear functions sampled at
// 196608 uniform points. Output [8, 196608] fp32 = 6.29MB (L2-resident).
// Branchless hot path: dual binary search per float4 + predicated selects.

#define S_TOTAL 196608
#define NB 8
#define NSEG 32
#define NP1 33
#define THREADS 256
#define PIX_PER_BLOCK (THREADS * 4)                 // 1024
#define BLOCKS_PER_BATCH (S_TOTAL / PIX_PER_BLOCK)  // 192

__global__ __launch_bounds__(THREADS) void decoder_pwl_kernel(
    const float* __restrict__ segx,
    const float* __restrict__ segy,
    float* __restrict__ out)
{
    __shared__ float  xs[NP1];    // fixed (running-max) knots
    __shared__ float4 cf[NSEG];   // per-segment {x, y, slope, pad}

    const int b = blockIdx.x / BLOCKS_PER_BATCH;
    const int chunk = blockIdx.x - b * BLOCKS_PER_BATCH;
    const int tid = threadIdx.x;

    // ---- Prologue: warp 0 parallel max-scan over 33 knots (ties -> later) ----
    if (tid < 32) {
        const int lane = tid;
        const float* px = segx + b * NP1;
        const float* py = segy + b * NP1;
        const float x0v = px[0];
        const float y0v = py[0];
        float xv = px[lane + 1];
        float yv = py[lane + 1];
        #pragma unroll
        for (int d = 1; d < 32; d <<= 1) {
            float ox = __shfl_up_sync(0xffffffffu, xv, d);
            float oy = __shfl_up_sync(0xffffffffu, yv, d);
            if (lane >= d && ox > xv) { xv = ox; yv = oy; }
        }
        if (x0v > xv) { xv = x0v; yv = y0v; }       // fold in knot 0 as prefix
        float xp = __shfl_up_sync(0xffffffffu, xv, 1);
        float yp = __shfl_up_sync(0xffffffffu, yv, 1);
        if (lane == 0) { xp = x0v; yp = y0v; }
        float dd = xv - xp;
        if (dd == 0.0f) dd = 0.0001f;
        xs[lane] = xp;                               // knot l (l = 0..31)
        cf[lane] = make_float4(xp, yp, (yv - yp) / dd, 0.0f);
        if (lane == 31) xs[32] = xv;
    }
    __syncthreads();

    // ---- Main: one float4 (4 contiguous pixels) per thread ----
    const float inv = 1.0f / (float)S_TOTAL;         // <=1ulp vs IEEE div; tol 1e-3
    const int s = chunk * PIX_PER_BLOCK + tid * 4;

    // Two independent predicated binary searches: largest j in [0,31]
    // with xs[j] <= x  (reproduces interior one-hot mask AND both clamps).
    const float x0 = (float)(s + 1) * inv;
    const float x3 = (float)(s + 4) * inv;
    int j0 = 0, j3 = 0;
    #pragma unroll
    for (int st = 16; st >= 1; st >>= 1) {
        if (xs[j0 + st] <= x0) j0 += st;
        if (xs[j3 + st] <= x3) j3 += st;
    }

    float4 o;
    float* ov = &o.x;
    if (j3 <= j0 + 1) {
        // Common case (all but ~256 of 393216 float4s): at most one knot
        // boundary inside this float4 -> branchless per-pixel select.
        const float  xb = xs[j3];                    // boundary knot
        const float4 c0 = cf[j0];
        const float4 c1 = cf[j3];
        #pragma unroll
        for (int e = 0; e < 4; e++) {
            float xin = (float)(s + 1 + e) * inv;
            bool hi = (xin >= xb);
            float cx = hi ? c1.x : c0.x;
            float cy = hi ? c1.y : c0.y;
            float cr = hi ? c1.z : c0.z;
            ov[e] = fmaf(cr, xin - cx, cy);          // same arith order as ref
        }
    } else {
        // Rare: >=2 knots inside a 4-pixel span (incl. duplicate knots).
        #pragma unroll
        for (int e = 0; e < 4; e++) {
            float xin = (float)(s + 1 + e) * inv;
            int j = 0;
            #pragma unroll
            for (int st = 16; st >= 1; st >>= 1) {
                if (xs[j + st] <= xin) j += st;
            }
            float4 c = cf[j];
            ov[e] = fmaf(c.z, xin - c.x, c.y);
        }
    }

    reinterpret_cast<float4*>(out)[b * (S_TOTAL / 4) + chunk * (PIX_PER_BLOCK / 4) + tid] = o;
}

extern "C" void kernel_launch(void* const* d_in, const int* in_sizes, int n_in,
                              void* d_out, int out_size) {
    const float* segx = (const float*)d_in[0];
    const float* segy = (const float*)d_in[1];
    float* out = (float*)d_out;

    const int blocks = NB * BLOCKS_PER_BATCH;        // 1536
    decoder_pwl_kernel<<<blocks, THREADS>>>(segx, segy, out);
}

// round 4
// speedup vs baseline: 1.3575x; 1.3575x over previous
#include <cuda_runtime.h>

// Decoder: 8 batches of 32-segment piecewise-linear functions sampled at
// 196608 uniform points. Output [8, 196608] fp32 = 6.29MB (L2-resident).
// Block-level segment search: lane 0 locates the (at most one) knot boundary
// inside the block's 2048-pixel span; all threads run a branchless select.

#define S_TOTAL 196608
#define NB 8
#define NSEG 32
#define NP1 33
#define THREADS 256
#define ITERS 2                                     // float4s per thread
#define PIX_PER_BLOCK (THREADS * ITERS * 4)         // 2048
#define BLOCKS_PER_BATCH (S_TOTAL / PIX_PER_BLOCK)  // 96

__global__ __launch_bounds__(THREADS) void decoder_pwl_kernel(
    const float* __restrict__ segx,
    const float* __restrict__ segy,
    float* __restrict__ out)
{
    __shared__ float  xs[NP1];    // fixed (running-max) knots
    __shared__ float4 cf[NSEG];   // per-segment {x, y, slope, pad} (fallback)
    __shared__ float4 sh_c0, sh_c1;
    __shared__ float  sh_xb;
    __shared__ int    sh_fb;

    const int b = blockIdx.x / BLOCKS_PER_BATCH;
    const int chunk = blockIdx.x - b * BLOCKS_PER_BATCH;
    const int tid = threadIdx.x;
    const int s_base = chunk * PIX_PER_BLOCK;
    const float inv = 1.0f / (float)S_TOTAL;        // <=1ulp vs IEEE div; tol 1e-3

    // ---- Prologue: warp 0 parallel max-scan over 33 knots (ties -> later) ----
    if (tid < 32) {
        const int lane = tid;
        const float* px = segx + b * NP1;
        const float* py = segy + b * NP1;
        const float x0v = px[0];
        const float y0v = py[0];
        float xv = px[lane + 1];
        float yv = py[lane + 1];
        #pragma unroll
        for (int d = 1; d < 32; d <<= 1) {
            float ox = __shfl_up_sync(0xffffffffu, xv, d);
            float oy = __shfl_up_sync(0xffffffffu, yv, d);
            if (lane >= d && ox > xv) { xv = ox; yv = oy; }
        }
        if (x0v > xv) { xv = x0v; yv = y0v; }       // fold in knot 0 as prefix
        float xp = __shfl_up_sync(0xffffffffu, xv, 1);
        float yp = __shfl_up_sync(0xffffffffu, yv, 1);
        if (lane == 0) { xp = x0v; yp = y0v; }
        float dd = xv - xp;
        if (dd == 0.0f) dd = 0.0001f;
        xs[lane] = xp;                               // knot l (l = 0..31)
        cf[lane] = make_float4(xp, yp, (yv - yp) / dd, 0.0f);
        if (lane == 31) xs[32] = xv;
        __syncwarp();

        // Lane 0: segment of block's first and last pixel.
        // j = largest k in [0,31] with xs[k] <= x  (handles both clamps too).
        if (lane == 0) {
            const float x_lo = (float)(s_base + 1) * inv;
            const float x_hi = (float)(s_base + PIX_PER_BLOCK) * inv;
            int jl = 0, jh = 0;
            #pragma unroll
            for (int st = 16; st >= 1; st >>= 1) {
                if (xs[jl + st] <= x_lo) jl += st;
                if (xs[jh + st] <= x_hi) jh += st;
            }
            sh_fb = (jh > jl + 1);                   // >=2 boundaries in block
            sh_xb = xs[jh];                          // the single boundary knot
            sh_c0 = cf[jl];
            sh_c1 = cf[jh];
        }
    }
    __syncthreads();

    float4* out4 = reinterpret_cast<float4*>(out);
    const int obase = b * (S_TOTAL / 4) + (s_base >> 2) + tid;

    if (!sh_fb) {
        // Common case: whole block within segments {jl, jh}, jh<=jl+1.
        const float  xb = sh_xb;
        const float4 c0 = sh_c0;
        const float4 c1 = sh_c1;
        #pragma unroll
        for (int i = 0; i < ITERS; i++) {
            const int s = s_base + (i * THREADS + tid) * 4;
            float4 o;
            float* ov = &o.x;
            #pragma unroll
            for (int e = 0; e < 4; e++) {
                float xin = (float)(s + 1 + e) * inv;
                bool hi = (xin >= xb);
                float cx = hi ? c1.x : c0.x;
                float cy = hi ? c1.y : c0.y;
                float cr = hi ? c1.z : c0.z;
                ov[e] = fmaf(cr, xin - cx, cy);      // same arith order as ref
            }
            out4[obase + i * THREADS] = o;
        }
    } else {
        // Rare: multiple knots inside this block -> per-pixel search.
        #pragma unroll
        for (int i = 0; i < ITERS; i++) {
            const int s = s_base + (i * THREADS + tid) * 4;
            float4 o;
            float* ov = &o.x;
            #pragma unroll
            for (int e = 0; e < 4; e++) {
                float xin = (float)(s + 1 + e) * inv;
                int j = 0;
                #pragma unroll
                for (int st = 16; st >= 1; st >>= 1) {
                    if (xs[j + st] <= xin) j += st;
                }
                float4 c = cf[j];
                ov[e] = fmaf(c.z, xin - c.x, c.y);
            }
            out4[obase + i * THREADS] = o;
        }
    }
}

extern "C" void kernel_launch(void* const* d_in, const int* in_sizes, int n_in,
                              void* d_out, int out_size) {
    const float* segx = (const float*)d_in[0];
    const float* segy = (const float*)d_in[1];
    float* out = (float*)d_out;

    const int blocks = NB * BLOCKS_PER_BATCH;        // 768
    decoder_pwl_kernel<<<blocks, THREADS>>>(segx, segy, out);
}